// round 1
// baseline (speedup 1.0000x reference)
#include <cuda_runtime.h>

// Problem constants
#define BB 16
#define CC 256
#define HH 64
#define WW 64
#define HWS 4096          // H*W
#define NPIX 65536        // B*H*W
#define DD 2048
#define MOM 0.99f
#define OMM 0.01f
#define EPSV 1e-5f

// Output layout (float32, concatenated in reference return order)
#define OFF_Q    0
#define OFF_LOSS 16777216
#define OFF_IDS  16777217
#define OFF_NE   16842753
#define OFF_NCS  17367041
#define OFF_NEA  17369089

// Scratch (no allocations allowed -> device globals)
__device__ float g_embed_norm[DD];
__device__ int   g_ids[NPIX];          // id per pixel in spatial (b,h,w) order
__device__ float g_counts[DD];
__device__ float g_embed_sum[CC * DD]; // (c, D)
__device__ float g_inv_cs[DD];
__device__ float g_sse;

// ---------------------------------------------------------------------------
// K0: zero accumulators (must run every launch: graph replays)
// ---------------------------------------------------------------------------
__global__ void k_zero() {
    int idx = blockIdx.x * 256 + threadIdx.x;
    if (idx < CC * DD)            g_embed_sum[idx] = 0.f;
    else if (idx < CC * DD + DD)  g_counts[idx - CC * DD] = 0.f;
    else if (idx == CC * DD + DD) g_sse = 0.f;
}

// ---------------------------------------------------------------------------
// K0b: codebook row norms |e_d|^2
// ---------------------------------------------------------------------------
__global__ void k_norm(const float* __restrict__ embed) {
    int warp = threadIdx.x >> 5;
    int lane = threadIdx.x & 31;
    int d = blockIdx.x * 8 + warp;
    const float* row = embed + d * CC;
    float s = 0.f;
#pragma unroll
    for (int j = 0; j < 8; j++) { float v = row[lane + 32 * j]; s = fmaf(v, v, s); }
#pragma unroll
    for (int o = 16; o; o >>= 1) s += __shfl_xor_sync(0xffffffffu, s, o);
    if (lane == 0) g_embed_norm[d] = s;
}

// ---------------------------------------------------------------------------
// K1: fused SGEMM + argmax.
// Pixels tiled in spatial order m = b*4096 + h*64 + w (x is s-contiguous).
// Block: 128 pixels x (all 2048 codes, 16 N-tiles of 128), K=256 in chunks of 16.
// 256 threads, 8x8 register microtile.
// ---------------------------------------------------------------------------
__global__ __launch_bounds__(256, 2)
void k_assign(const float* __restrict__ x, const float* __restrict__ embed,
              float* __restrict__ out_ids) {
    __shared__ float As[16][128];
    __shared__ float Bs[16][128];

    const int tid = threadIdx.x;
    const int tx = tid & 15, ty = tid >> 4;
    const int m0 = blockIdx.x * 128;                 // 4096 % 128 == 0: no batch crossing
    const float* xb = x + (m0 >> 12) * (CC * HWS) + (m0 & 4095);

    const int a_m = (tid & 31) * 4;                  // A load: float4 along m
    const int a_k = tid >> 5;                        // k rows a_k and a_k+8
    const int b_d = tid >> 1;                        // B load: 8 contiguous k per d
    const int b_k = (tid & 1) * 8;

    float bestS[8];
    int   bestI[8];
#pragma unroll
    for (int i = 0; i < 8; i++) { bestS[i] = -3.4e38f; bestI[i] = 0; }

    for (int nt = 0; nt < 16; nt++) {
        const int d0 = nt * 128;
        float acc[8][8];
#pragma unroll
        for (int i = 0; i < 8; i++)
#pragma unroll
            for (int j = 0; j < 8; j++) acc[i][j] = 0.f;

        for (int kk = 0; kk < 16; kk++) {
            __syncthreads();
            // A tile: As[k][m] = x[b, kk*16+k, s0+m]
            const float* pa = xb + (kk * 16 + a_k) * HWS + a_m;
            float4 va0 = *(const float4*)pa;
            float4 va1 = *(const float4*)(pa + 8 * HWS);
            *(float4*)&As[a_k][a_m]     = va0;
            *(float4*)&As[a_k + 8][a_m] = va1;
            // B tile (transposed store): Bs[k][d]
            const float* pb = embed + (d0 + b_d) * CC + kk * 16 + b_k;
            float4 vb0 = *(const float4*)pb;
            float4 vb1 = *(const float4*)(pb + 4);
            Bs[b_k + 0][b_d] = vb0.x; Bs[b_k + 1][b_d] = vb0.y;
            Bs[b_k + 2][b_d] = vb0.z; Bs[b_k + 3][b_d] = vb0.w;
            Bs[b_k + 4][b_d] = vb1.x; Bs[b_k + 5][b_d] = vb1.y;
            Bs[b_k + 6][b_d] = vb1.z; Bs[b_k + 7][b_d] = vb1.w;
            __syncthreads();
#pragma unroll
            for (int k = 0; k < 16; k++) {
                float ra[8], rb[8];
                *(float4*)&ra[0] = *(float4*)&As[k][ty * 8];
                *(float4*)&ra[4] = *(float4*)&As[k][ty * 8 + 4];
                *(float4*)&rb[0] = *(float4*)&Bs[k][tx * 8];
                *(float4*)&rb[4] = *(float4*)&Bs[k][tx * 8 + 4];
#pragma unroll
                for (int i = 0; i < 8; i++)
#pragma unroll
                    for (int j = 0; j < 8; j++) acc[i][j] = fmaf(ra[i], rb[j], acc[i][j]);
            }
        }
        // score = 2*dot - |e_d|^2  (the -|x|^2 term is constant per pixel -> dropped)
#pragma unroll
        for (int j = 0; j < 8; j++) {
            const int d_id = d0 + tx * 8 + j;
            const float nrm = g_embed_norm[d_id];
#pragma unroll
            for (int i = 0; i < 8; i++) {
                float s = 2.f * acc[i][j] - nrm;
                if (s > bestS[i]) { bestS[i] = s; bestI[i] = d_id; }
            }
        }
    }

    // reduce across the 16 tx lanes of each ty row (contiguous 16-lane segment)
#pragma unroll
    for (int i = 0; i < 8; i++) {
        float s = bestS[i]; int id = bestI[i];
#pragma unroll
        for (int off = 8; off; off >>= 1) {
            float so = __shfl_xor_sync(0xffffffffu, s, off, 16);
            int   io = __shfl_xor_sync(0xffffffffu, id, off, 16);
            if (so > s || (so == s && io < id)) { s = so; id = io; }  // first-max tiebreak
        }
        if (tx == 0) {
            int m = m0 + ty * 8 + i;
            g_ids[m] = id;
            int sloc = m & 4095;
            // reference flat order n = b*4096 + w*64 + h
            int n = (m & ~4095) | ((sloc & 63) << 6) | (sloc >> 6);
            out_ids[n] = (float)id;
        }
    }
}

// ---------------------------------------------------------------------------
// K2: quantized write + commit-loss SSE + segment sums (counts, embed_sum)
// Block = 32 consecutive spatial pixels x 256 channels. Embed rows staged in
// padded smem so both x (s-contiguous) and embed (c-contiguous) reads coalesce.
// ---------------------------------------------------------------------------
__global__ __launch_bounds__(256)
void k_quant(const float* __restrict__ x, const float* __restrict__ embed,
             float* __restrict__ out_q) {
    __shared__ float qs[32][257];
    __shared__ int   sid[32];
    __shared__ float red[8];

    const int t = threadIdx.x;
    const int lane = t & 31, warp = t >> 5;
    const int m0 = blockIdx.x * 32;
    const int b = m0 >> 12;
    const int s0 = m0 & 4095;

    if (t < 32) sid[t] = g_ids[m0 + t];
    __syncthreads();
#pragma unroll
    for (int r = 0; r < 4; r++) {
        const int p = warp + r * 8;
        const float* row = embed + sid[p] * CC;
#pragma unroll
        for (int j = 0; j < 8; j++) qs[p][lane + 32 * j] = row[lane + 32 * j];
    }
    __syncthreads();

    const float* xb = x + b * (CC * HWS) + s0;
    float* qb = out_q + b * (CC * HWS) + s0;
    const int myid = sid[lane];
    float lsum = 0.f;
#pragma unroll
    for (int ci = 0; ci < 32; ci++) {
        const int c = warp + ci * 8;
        float xv = xb[c * HWS + lane];
        float qv = qs[lane][c];
        qb[c * HWS + lane] = qv;
        float dd = xv - qv;
        lsum = fmaf(dd, dd, lsum);
        atomicAdd(&g_embed_sum[c * DD + myid], xv);
    }
    if (warp == 0) atomicAdd(&g_counts[myid], 1.0f);

#pragma unroll
    for (int o = 16; o; o >>= 1) lsum += __shfl_xor_sync(0xffffffffu, lsum, o);
    if (lane == 0) red[warp] = lsum;
    __syncthreads();
    if (t == 0) {
        float s = 0.f;
#pragma unroll
        for (int i = 0; i < 8; i++) s += red[i];
        atomicAdd(&g_sse, s);
    }
}

// ---------------------------------------------------------------------------
// K3a: new_cluster_size, n, smoothing reciprocal, loss scalar (single block)
// ---------------------------------------------------------------------------
__global__ void k_stats(const float* __restrict__ cs, float* __restrict__ out_ncs,
                        float* __restrict__ out_loss) {
    __shared__ float red[32];
    const int t = threadIdx.x;  // 1024 threads
    const int d0 = t, d1 = t + 1024;
    float n0 = MOM * cs[d0] + OMM * g_counts[d0];
    float n1 = MOM * cs[d1] + OMM * g_counts[d1];
    out_ncs[d0] = n0;
    out_ncs[d1] = n1;
    float s = n0 + n1;
#pragma unroll
    for (int o = 16; o; o >>= 1) s += __shfl_xor_sync(0xffffffffu, s, o);
    if ((t & 31) == 0) red[t >> 5] = s;
    __syncthreads();
    if (t < 32) {
        float v = red[t];
#pragma unroll
        for (int o = 16; o; o >>= 1) v += __shfl_xor_sync(0xffffffffu, v, o);
        if (t == 0) red[0] = v;
    }
    __syncthreads();
    const float n = red[0];
    const float scale = (n + (float)DD * EPSV) / n;   // 1/cs_smoothed = scale/(ncs+eps)
    g_inv_cs[d0] = scale / (n0 + EPSV);
    g_inv_cs[d1] = scale / (n1 + EPSV);
    if (t == 0) out_loss[0] = g_sse * (1.f / 16777216.f);
}

// ---------------------------------------------------------------------------
// K3b: new_embed_avg (c,D) + new_embed (D,c)
// ---------------------------------------------------------------------------
__global__ void k_embed_out(const float* __restrict__ embed_avg,
                            float* __restrict__ out_nea, float* __restrict__ out_ne) {
    const int idx = blockIdx.x * 256 + threadIdx.x;   // idx = c*2048 + d
    const int c = idx >> 11, d = idx & 2047;
    float nea = MOM * embed_avg[idx] + OMM * g_embed_sum[idx];
    out_nea[idx] = nea;
    out_ne[d * CC + c] = nea * g_inv_cs[d];
}

// ---------------------------------------------------------------------------
extern "C" void kernel_launch(void* const* d_in, const int* in_sizes, int n_in,
                              void* d_out, int out_size) {
    const float* x     = (const float*)d_in[0];
    const float* embed = (const float*)d_in[1];
    const float* cs    = (const float*)d_in[2];
    const float* ea    = (const float*)d_in[3];
    float* out = (float*)d_out;

    float* out_q    = out + OFF_Q;
    float* out_loss = out + OFF_LOSS;
    float* out_ids  = out + OFF_IDS;
    float* out_ne   = out + OFF_NE;
    float* out_ncs  = out + OFF_NCS;
    float* out_nea  = out + OFF_NEA;

    k_zero<<<(CC * DD + DD + 1 + 255) / 256, 256>>>();
    k_norm<<<DD / 8, 256>>>(embed);
    k_assign<<<NPIX / 128, 256>>>(x, embed, out_ids);
    k_quant<<<NPIX / 32, 256>>>(x, embed, out_q);
    k_stats<<<1, 1024>>>(cs, out_ncs, out_loss);
    k_embed_out<<<(CC * DD) / 256, 256>>>(ea, out_nea, out_ne);
}

// round 6
// speedup vs baseline: 2.2572x; 2.2572x over previous
#include <cuda_runtime.h>
#include <cuda_fp16.h>
#include <cstdint>

// Problem constants
#define BB 16
#define CC 256
#define HWS 4096
#define NPIX 65536
#define DD 2048
#define MOM 0.99f
#define OMM 0.01f
#define EPSV 1e-5f

// Output layout (float32, reference return order)
#define OFF_Q    0
#define OFF_LOSS 16777216
#define OFF_IDS  16777217
#define OFF_NE   16842753
#define OFF_NCS  17367041
#define OFF_NEA  17369089

#define NKC 17   // K chunks of 16 over K'=257 (chunk 16 holds only the fold column k=256)

// Scratch (small device globals only — total < 5 MB)
__device__ __align__(16) unsigned char g_Bpl[16u*NKC*8192u]; // [ntile][kchunk] 8KB: fp16 hi/lo embed planes + fold col -|e|^2
__device__ float g_embed_norm[DD];
__device__ int   g_ids[NPIX];
__device__ float g_counts[DD];
__device__ float g_embed_sum[CC * DD];
__device__ float g_inv_cs[DD];
__device__ float g_sse;

// ---------------- PTX helpers (sm_80-baseline features only) ----------------
__device__ __forceinline__ uint32_t smem_u32(const void* p) {
    uint32_t a;
    asm("{ .reg .u64 t; cvta.to.shared.u64 t, %1; cvt.u32.u64 %0, t; }" : "=r"(a) : "l"(p));
    return a;
}
#define CP16(dst, src) asm volatile("cp.async.cg.shared.global [%0], [%1], 16;" :: "r"(dst), "l"(src))
#define CP_COMMIT() asm volatile("cp.async.commit_group;" ::: "memory")
#define CP_WAIT1()  asm volatile("cp.async.wait_group 1;" ::: "memory")
#define CP_WAIT0()  asm volatile("cp.async.wait_group 0;" ::: "memory")

#define LDSM_X4(r0,r1,r2,r3,addr) \
    asm volatile("ldmatrix.sync.aligned.m8n8.x4.shared.b16 {%0,%1,%2,%3}, [%4];" \
        : "=r"(r0),"=r"(r1),"=r"(r2),"=r"(r3) : "r"(addr))
#define LDSM_X4_T(r0,r1,r2,r3,addr) \
    asm volatile("ldmatrix.sync.aligned.m8n8.x4.trans.shared.b16 {%0,%1,%2,%3}, [%4];" \
        : "=r"(r0),"=r"(r1),"=r"(r2),"=r"(r3) : "r"(addr))

#define MMA16816(c, a0,a1,a2,a3, b0,b1) \
    asm volatile("mma.sync.aligned.m16n8k16.row.col.f32.f16.f16.f32 " \
        "{%0,%1,%2,%3}, {%4,%5,%6,%7}, {%8,%9}, {%0,%1,%2,%3};" \
        : "+f"((c)[0]),"+f"((c)[1]),"+f"((c)[2]),"+f"((c)[3]) \
        : "r"(a0),"r"(a1),"r"(a2),"r"(a3),"r"(b0),"r"(b1))

// ---------------------------------------------------------------------------
__global__ void k_zero() {
    int idx = blockIdx.x * 256 + threadIdx.x;
    if (idx < CC * DD)            g_embed_sum[idx] = 0.f;
    else if (idx < CC * DD + DD)  g_counts[idx - CC * DD] = 0.f;
    else if (idx == CC * DD + DD) g_sse = 0.f;
}

__global__ void k_norm(const float* __restrict__ embed) {
    int warp = threadIdx.x >> 5, lane = threadIdx.x & 31;
    int d = blockIdx.x * 8 + warp;
    const float* row = embed + d * CC;
    float s = 0.f;
#pragma unroll
    for (int j = 0; j < 8; j++) { float v = row[lane + 32 * j]; s = fmaf(v, v, s); }
#pragma unroll
    for (int o = 16; o; o >>= 1) s += __shfl_xor_sync(0xffffffffu, s, o);
    if (lane == 0) g_embed_norm[d] = s;
}

// ---------------------------------------------------------------------------
// prep_B: embed -> fp16 hi/lo planes (+ fold column -|e|^2 at k=256).
// Chunk (nt, kc) = 8KB: [plane 2][k 16][swizzled 16B unit = 8 consecutive n]
// swz(nblk,k) = (nblk&8) | ((nblk ^ (k&7)) & 7)  -> conflict-free ldmatrix.trans
// ---------------------------------------------------------------------------
__global__ __launch_bounds__(256) void prep_B(const float* __restrict__ embed) {
    const int nt = blockIdx.x / NKC, kc = blockIdx.x % NKC;
    const int t = threadIdx.x;
    const int k = t >> 4, nblk = t & 15;
    const int kglob = kc * 16 + k;
    const int n0 = nt * 128 + nblk * 8;
    uint32_t hu[4], lu[4];
#pragma unroll
    for (int nn = 0; nn < 8; nn += 2) {
        const int na = n0 + nn, nb = n0 + nn + 1;
        float v0 = (kglob < 256) ? embed[na * CC + kglob] : (kglob == 256 ? -g_embed_norm[na] : 0.f);
        float v1 = (kglob < 256) ? embed[nb * CC + kglob] : (kglob == 256 ? -g_embed_norm[nb] : 0.f);
        __half h0 = __float2half_rn(v0), h1 = __float2half_rn(v1);
        __half l0 = __float2half_rn(v0 - __half2float(h0));
        __half l1 = __float2half_rn(v1 - __half2float(h1));
        hu[nn >> 1] = (uint32_t)__half_as_ushort(h0) | ((uint32_t)__half_as_ushort(h1) << 16);
        lu[nn >> 1] = (uint32_t)__half_as_ushort(l0) | ((uint32_t)__half_as_ushort(l1) << 16);
    }
    const int swz = (nblk & 8) | ((nblk ^ (k & 7)) & 7);
    unsigned char* ob = g_Bpl + ((size_t)(nt * NKC + kc) << 13);
    *(uint4*)(ob + k * 256 + swz * 16) = *(uint4*)hu;
    *(uint4*)(ob + 4096 + k * 256 + swz * 16) = *(uint4*)lu;
}

// ---------------------------------------------------------------------------
// k_assign_mma: 3xFP16 mma.sync GEMM + argmax, A converted on the fly.
// score = (2x | 1) . (e | -|e|^2)   (lo*lo term dropped: ~1e-6 abs vs gaps O(0.1))
// CTA = 128 pixels, 16 N-tiles of 128 codes, K chunks of 16.
// 8 warps (4M x 2N), warp tile 32x64.
// Static smem 24KB: A planes 8KB [plane2][j2][p128][16B] + B stages 2x8KB.
// ---------------------------------------------------------------------------
__global__ __launch_bounds__(256) void k_assign_mma(const float* __restrict__ x,
                                                    float* __restrict__ out_ids) {
    __shared__ __align__(16) unsigned char sm[24576];
    const uint32_t sbase = smem_u32(sm);
    const uint32_t APL = sbase;         // 8KB A planes
    const uint32_t BST = sbase + 8192;  // 2 x 8KB B stages
    const int tid = threadIdx.x;
    const int lane = tid & 31, wid = tid >> 5;
    const int wm0 = (wid >> 1) * 32;    // warp m base (4 rows of 32)
    const int ncol = wid & 1;
    const int wn0 = ncol * 64;          // warp n base within 128-tile
    const int mblk = blockIdx.x;

    // A loader role: thread -> (pixel p, k-octet j)
    const int p = tid & 127;
    const int j = tid >> 7;
    const int m = mblk * 128 + p;
    const float* xs = x + (m >> 12) * (CC * HWS) + (m & 4095);

#define ISSUE_B(stg, nt_, kc_) do { \
        uint32_t db = BST + (stg) * 8192 + tid * 16; \
        const unsigned char* sbp = g_Bpl + ((size_t)((nt_) * NKC + (kc_)) << 13) + tid * 16; \
        CP16(db, sbp); \
        CP16(db + 4096, sbp + 4096); \
        CP_COMMIT(); \
    } while (0)

    float c[2][8][4];
#pragma unroll
    for (int a = 0; a < 2; a++)
#pragma unroll
        for (int b = 0; b < 8; b++)
#pragma unroll
            for (int r = 0; r < 4; r++) c[a][b][r] = 0.f;
    float bestS[4];
    int   bestI[4];
#pragma unroll
    for (int r = 0; r < 4; r++) { bestS[r] = -3.4e38f; bestI[r] = 0; }

    ISSUE_B(0, 0, 0);

    const int NIT = 16 * NKC;  // 272
    for (int idx = 0; idx < NIT; idx++) {
        const int nt = idx / NKC, kc = idx % NKC, buf = idx & 1;

        // 1) load + convert this A chunk into registers (overlaps barrier)
        uint32_t hu[4], lu[4];
        {
            const int k0 = kc * 16 + j * 8;
#pragma unroll
            for (int kk = 0; kk < 8; kk += 2) {
                const int ka = k0 + kk, kb = k0 + kk + 1;
                float v0 = (ka < 256) ? 2.f * xs[(size_t)ka * HWS] : (ka == 256 ? 1.f : 0.f);
                float v1 = (kb < 256) ? 2.f * xs[(size_t)kb * HWS] : (kb == 256 ? 1.f : 0.f);
                __half h0 = __float2half_rn(v0), h1 = __float2half_rn(v1);
                __half l0 = __float2half_rn(v0 - __half2float(h0));
                __half l1 = __float2half_rn(v1 - __half2float(h1));
                hu[kk >> 1] = (uint32_t)__half_as_ushort(h0) | ((uint32_t)__half_as_ushort(h1) << 16);
                lu[kk >> 1] = (uint32_t)__half_as_ushort(l0) | ((uint32_t)__half_as_ushort(l1) << 16);
            }
        }

        // 2) everyone finished last tile's ldmatrix -> A planes & old B stage are free
        __syncthreads();

        // 3) now safe to start filling the other B stage
        if (idx < NIT - 1) ISSUE_B((idx + 1) & 1, (idx + 1) / NKC, (idx + 1) % NKC);

        // 4) publish A planes
        *(uint4*)(sm + j * 2048 + p * 16)        = *(uint4*)hu;
        *(uint4*)(sm + 4096 + j * 2048 + p * 16) = *(uint4*)lu;

        // 5) B(idx) landed
        if (idx < NIT - 1) CP_WAIT1(); else CP_WAIT0();
        __syncthreads();

        const uint32_t sB = BST + buf * 8192;

        // B fragments: [plane][npair][4] — one x4.trans covers 2 n8-blocks x k16
        uint32_t bf[2][4][4];
        const int g = lane >> 3;
        {
            const int kk = ((g & 1) << 3) | (lane & 7);
            const int nbg = g >> 1;
#pragma unroll
            for (int pp = 0; pp < 2; pp++)
#pragma unroll
                for (int np = 0; np < 4; np++) {
                    const int nblk = ((wn0 + np * 16) >> 3) + nbg;
                    const uint32_t addr = sB + pp * 4096 + kk * 256 +
                        (((nblk & 8) | ((nblk ^ (kk & 7)) & 7)) << 4);
                    LDSM_X4_T(bf[pp][np][0], bf[pp][np][1], bf[pp][np][2], bf[pp][np][3], addr);
                }
        }
#pragma unroll
        for (int mt = 0; mt < 2; mt++) {
            const int mrow = wm0 + mt * 16 + (g & 1) * 8 + (lane & 7);
            uint32_t aH[4], aL[4];
            const uint32_t aaddr = APL + (g >> 1) * 2048 + mrow * 16;
            LDSM_X4(aH[0], aH[1], aH[2], aH[3], aaddr);
            LDSM_X4(aL[0], aL[1], aL[2], aL[3], aaddr + 4096);
#pragma unroll
            for (int np = 0; np < 4; np++) {
                MMA16816(c[mt][2*np],   aH[0],aH[1],aH[2],aH[3], bf[0][np][0], bf[0][np][1]);
                MMA16816(c[mt][2*np],   aH[0],aH[1],aH[2],aH[3], bf[1][np][0], bf[1][np][1]);
                MMA16816(c[mt][2*np],   aL[0],aL[1],aL[2],aL[3], bf[0][np][0], bf[0][np][1]);
                MMA16816(c[mt][2*np+1], aH[0],aH[1],aH[2],aH[3], bf[0][np][2], bf[0][np][3]);
                MMA16816(c[mt][2*np+1], aH[0],aH[1],aH[2],aH[3], bf[1][np][2], bf[1][np][3]);
                MMA16816(c[mt][2*np+1], aL[0],aL[1],aL[2],aL[3], bf[0][np][2], bf[0][np][3]);
            }
        }

        if (kc == NKC - 1) {
            // accumulators ARE the scores; running argmax (ascending n, strict >), reset
            const int nb0 = nt * 128 + wn0 + (lane & 3) * 2;
#pragma unroll
            for (int mt = 0; mt < 2; mt++)
#pragma unroll
                for (int tn = 0; tn < 8; tn++) {
                    const int n = nb0 + tn * 8;
                    const float s0 = c[mt][tn][0];
                    const float s1 = c[mt][tn][1];
                    const float s2 = c[mt][tn][2];
                    const float s3 = c[mt][tn][3];
                    const int b0 = mt * 2, b1 = mt * 2 + 1;
                    if (s0 > bestS[b0]) { bestS[b0] = s0; bestI[b0] = n; }
                    if (s1 > bestS[b0]) { bestS[b0] = s1; bestI[b0] = n + 1; }
                    if (s2 > bestS[b1]) { bestS[b1] = s2; bestI[b1] = n; }
                    if (s3 > bestS[b1]) { bestS[b1] = s3; bestI[b1] = n + 1; }
                    c[mt][tn][0] = 0.f; c[mt][tn][1] = 0.f;
                    c[mt][tn][2] = 0.f; c[mt][tn][3] = 0.f;
                }
        }
    }

    __syncthreads();  // drain; reuse smem for cross-warp reduce
    float* redS = (float*)sm;
    int*   redI = (int*)(sm + 512);

    // reduce across lane quads (lanes 4q..4q+3 share rows q and q+8 of each m16 tile)
    float rs[4]; int ri[4];
#pragma unroll
    for (int r = 0; r < 4; r++) {
        float s = bestS[r]; int i = bestI[r];
#pragma unroll
        for (int off = 1; off <= 2; off <<= 1) {
            float so = __shfl_xor_sync(0xffffffffu, s, off);
            int   io = __shfl_xor_sync(0xffffffffu, i, off);
            if (so > s || (so == s && io < i)) { s = so; i = io; }
        }
        rs[r] = s; ri[r] = i;
    }
    if (ncol == 0 && (lane & 3) == 0) {
#pragma unroll
        for (int r = 0; r < 4; r++) {
            const int rl = wm0 + (r >> 1) * 16 + (r & 1) * 8 + (lane >> 2);
            redS[rl] = rs[r]; redI[rl] = ri[r];
        }
    }
    __syncthreads();
    if (ncol == 1 && (lane & 3) == 0) {
#pragma unroll
        for (int r = 0; r < 4; r++) {
            const int rl = wm0 + (r >> 1) * 16 + (r & 1) * 8 + (lane >> 2);
            float s = rs[r]; int i = ri[r];
            const float so = redS[rl]; const int io = redI[rl];
            if (so > s || (so == s && io < i)) { s = so; i = io; }
            const int mm = mblk * 128 + rl;
            g_ids[mm] = i;
            const int sp = mm & 4095;
            out_ids[(mm & ~4095) | ((sp & 63) << 6) | (sp >> 6)] = (float)i;
        }
    }
}

// ---------------------------------------------------------------------------
// K2: quantized write + commit-loss SSE + segment sums (proven R1 code)
// ---------------------------------------------------------------------------
__global__ __launch_bounds__(256)
void k_quant(const float* __restrict__ x, const float* __restrict__ embed,
             float* __restrict__ out_q) {
    __shared__ float qs[32][257];
    __shared__ int   sid[32];
    __shared__ float red[8];

    const int t = threadIdx.x;
    const int lane = t & 31, warp = t >> 5;
    const int m0 = blockIdx.x * 32;
    const int b = m0 >> 12;
    const int s0 = m0 & 4095;

    if (t < 32) sid[t] = g_ids[m0 + t];
    __syncthreads();
#pragma unroll
    for (int r = 0; r < 4; r++) {
        const int pp = warp + r * 8;
        const float* row = embed + sid[pp] * CC;
#pragma unroll
        for (int jj = 0; jj < 8; jj++) qs[pp][lane + 32 * jj] = row[lane + 32 * jj];
    }
    __syncthreads();

    const float* xb = x + b * (CC * HWS) + s0;
    float* qb = out_q + b * (CC * HWS) + s0;
    const int myid = sid[lane];
    float lsum = 0.f;
#pragma unroll
    for (int ci = 0; ci < 32; ci++) {
        const int cc = warp + ci * 8;
        float xv = xb[cc * HWS + lane];
        float qv = qs[lane][cc];
        qb[cc * HWS + lane] = qv;
        float dd = xv - qv;
        lsum = fmaf(dd, dd, lsum);
        atomicAdd(&g_embed_sum[cc * DD + myid], xv);
    }
    if (warp == 0) atomicAdd(&g_counts[myid], 1.0f);

#pragma unroll
    for (int o = 16; o; o >>= 1) lsum += __shfl_xor_sync(0xffffffffu, lsum, o);
    if (lane == 0) red[warp] = lsum;
    __syncthreads();
    if (t == 0) {
        float s = 0.f;
#pragma unroll
        for (int i = 0; i < 8; i++) s += red[i];
        atomicAdd(&g_sse, s);
    }
}

__global__ void k_stats(const float* __restrict__ cs, float* __restrict__ out_ncs,
                        float* __restrict__ out_loss) {
    __shared__ float red[32];
    const int t = threadIdx.x;
    const int d0 = t, d1 = t + 1024;
    float n0 = MOM * cs[d0] + OMM * g_counts[d0];
    float n1 = MOM * cs[d1] + OMM * g_counts[d1];
    out_ncs[d0] = n0;
    out_ncs[d1] = n1;
    float s = n0 + n1;
#pragma unroll
    for (int o = 16; o; o >>= 1) s += __shfl_xor_sync(0xffffffffu, s, o);
    if ((t & 31) == 0) red[t >> 5] = s;
    __syncthreads();
    if (t < 32) {
        float v = red[t];
#pragma unroll
        for (int o = 16; o; o >>= 1) v += __shfl_xor_sync(0xffffffffu, v, o);
        if (t == 0) red[0] = v;
    }
    __syncthreads();
    const float n = red[0];
    const float scale = (n + (float)DD * EPSV) / n;
    g_inv_cs[d0] = scale / (n0 + EPSV);
    g_inv_cs[d1] = scale / (n1 + EPSV);
    if (t == 0) out_loss[0] = g_sse * (1.f / 16777216.f);
}

__global__ void k_embed_out(const float* __restrict__ embed_avg,
                            float* __restrict__ out_nea, float* __restrict__ out_ne) {
    const int idx = blockIdx.x * 256 + threadIdx.x;
    const int cc = idx >> 11, d = idx & 2047;
    float nea = MOM * embed_avg[idx] + OMM * g_embed_sum[idx];
    out_nea[idx] = nea;
    out_ne[d * CC + cc] = nea * g_inv_cs[d];
}

// ---------------------------------------------------------------------------
extern "C" void kernel_launch(void* const* d_in, const int* in_sizes, int n_in,
                              void* d_out, int out_size) {
    const float* x     = (const float*)d_in[0];
    const float* embed = (const float*)d_in[1];
    const float* cs    = (const float*)d_in[2];
    const float* ea    = (const float*)d_in[3];
    float* out = (float*)d_out;

    k_zero<<<(CC * DD + DD + 1 + 255) / 256, 256>>>();
    k_norm<<<DD / 8, 256>>>(embed);
    prep_B<<<16 * NKC, 256>>>(embed);
    k_assign_mma<<<NPIX / 128, 256>>>(x, out + OFF_IDS);
    k_quant<<<NPIX / 32, 256>>>(x, embed, out + OFF_Q);
    k_stats<<<1, 1024>>>(cs, out + OFF_NCS, out + OFF_LOSS);
    k_embed_out<<<(CC * DD) / 256, 256>>>(ea, out + OFF_NEA, out + OFF_NE);
}

// round 7
// speedup vs baseline: 2.7478x; 1.2174x over previous
#include <cuda_runtime.h>
#include <cuda_fp16.h>
#include <cstdint>

// Problem constants
#define BB 16
#define CC 256
#define HWS 4096
#define NPIX 65536
#define DD 2048
#define MOM 0.99f
#define OMM 0.01f
#define EPSV 1e-5f

// Output layout (float32, reference return order)
#define OFF_Q    0
#define OFF_LOSS 16777216
#define OFF_IDS  16777217
#define OFF_NE   16842753
#define OFF_NCS  17367041
#define OFF_NEA  17369089

#define NKC 17   // K chunks of 16 over K'=257 (chunk 16 holds only the fold column k=256)
#define NTP 8    // N-tile pairs (2048 codes / 256)
#define NIT (NTP * NKC)  // 136 mainloop iterations

// Dynamic smem layout for k_assign_mma2 (per CTA = 104448 B)
#define APL_OFF 0        // A planes: [kc 17][plane 2][oct 2][px 64] x 16B = 69632
#define BST_OFF 69632    // B stages: 2 x (2 chunks x 8KB) = 32768
#define RED_OFF 102400   // redS float[4][64] (1024) + redI int[4][64] (1024)
#define SMEM_DYN 104448

// Scratch (small device globals only)
__device__ __align__(16) unsigned char g_Bpl[16u*NKC*8192u]; // [ntile][kchunk] 8KB: fp16 hi/lo embed planes + fold col -|e|^2
__device__ float g_embed_norm[DD];
__device__ int   g_ids[NPIX];
__device__ float g_counts[DD];
__device__ float g_embed_sum[CC * DD];
__device__ float g_inv_cs[DD];
__device__ float g_sse;

// ---------------- PTX helpers (sm_80-baseline features only) ----------------
__device__ __forceinline__ uint32_t smem_u32(const void* p) {
    uint32_t a;
    asm("{ .reg .u64 t; cvta.to.shared.u64 t, %1; cvt.u32.u64 %0, t; }" : "=r"(a) : "l"(p));
    return a;
}
#define CP16(dst, src) asm volatile("cp.async.cg.shared.global [%0], [%1], 16;" :: "r"(dst), "l"(src))
#define CP_COMMIT() asm volatile("cp.async.commit_group;" ::: "memory")
#define CP_WAIT1()  asm volatile("cp.async.wait_group 1;" ::: "memory")
#define CP_WAIT0()  asm volatile("cp.async.wait_group 0;" ::: "memory")

#define LDSM_X4(r0,r1,r2,r3,addr) \
    asm volatile("ldmatrix.sync.aligned.m8n8.x4.shared.b16 {%0,%1,%2,%3}, [%4];" \
        : "=r"(r0),"=r"(r1),"=r"(r2),"=r"(r3) : "r"(addr))
#define LDSM_X4_T(r0,r1,r2,r3,addr) \
    asm volatile("ldmatrix.sync.aligned.m8n8.x4.trans.shared.b16 {%0,%1,%2,%3}, [%4];" \
        : "=r"(r0),"=r"(r1),"=r"(r2),"=r"(r3) : "r"(addr))

#define MMA16816(c, a0,a1,a2,a3, b0,b1) \
    asm volatile("mma.sync.aligned.m16n8k16.row.col.f32.f16.f16.f32 " \
        "{%0,%1,%2,%3}, {%4,%5,%6,%7}, {%8,%9}, {%0,%1,%2,%3};" \
        : "+f"((c)[0]),"+f"((c)[1]),"+f"((c)[2]),"+f"((c)[3]) \
        : "r"(a0),"r"(a1),"r"(a2),"r"(a3),"r"(b0),"r"(b1))

// ---------------------------------------------------------------------------
__global__ void k_zero() {
    int idx = blockIdx.x * 256 + threadIdx.x;
    if (idx < CC * DD)            g_embed_sum[idx] = 0.f;
    else if (idx < CC * DD + DD)  g_counts[idx - CC * DD] = 0.f;
    else if (idx == CC * DD + DD) g_sse = 0.f;
}

__global__ void k_norm(const float* __restrict__ embed) {
    int warp = threadIdx.x >> 5, lane = threadIdx.x & 31;
    int d = blockIdx.x * 8 + warp;
    const float* row = embed + d * CC;
    float s = 0.f;
#pragma unroll
    for (int j = 0; j < 8; j++) { float v = row[lane + 32 * j]; s = fmaf(v, v, s); }
#pragma unroll
    for (int o = 16; o; o >>= 1) s += __shfl_xor_sync(0xffffffffu, s, o);
    if (lane == 0) g_embed_norm[d] = s;
}

// ---------------------------------------------------------------------------
// prep_B: embed -> fp16 hi/lo planes (+ fold column -|e|^2 at k=256).
// Chunk (nt, kc) = 8KB: [plane 2][k 16][swizzled 16B unit = 8 consecutive n]
// ---------------------------------------------------------------------------
__global__ __launch_bounds__(256) void prep_B(const float* __restrict__ embed) {
    const int nt = blockIdx.x / NKC, kc = blockIdx.x % NKC;
    const int t = threadIdx.x;
    const int k = t >> 4, nblk = t & 15;
    const int kglob = kc * 16 + k;
    const int n0 = nt * 128 + nblk * 8;
    uint32_t hu[4], lu[4];
#pragma unroll
    for (int nn = 0; nn < 8; nn += 2) {
        const int na = n0 + nn, nb = n0 + nn + 1;
        float v0 = (kglob < 256) ? embed[na * CC + kglob] : (kglob == 256 ? -g_embed_norm[na] : 0.f);
        float v1 = (kglob < 256) ? embed[nb * CC + kglob] : (kglob == 256 ? -g_embed_norm[nb] : 0.f);
        __half h0 = __float2half_rn(v0), h1 = __float2half_rn(v1);
        __half l0 = __float2half_rn(v0 - __half2float(h0));
        __half l1 = __float2half_rn(v1 - __half2float(h1));
        hu[nn >> 1] = (uint32_t)__half_as_ushort(h0) | ((uint32_t)__half_as_ushort(h1) << 16);
        lu[nn >> 1] = (uint32_t)__half_as_ushort(l0) | ((uint32_t)__half_as_ushort(l1) << 16);
    }
    const int swz = (nblk & 8) | ((nblk ^ (k & 7)) & 7);
    unsigned char* ob = g_Bpl + ((size_t)(nt * NKC + kc) << 13);
    *(uint4*)(ob + k * 256 + swz * 16) = *(uint4*)hu;
    *(uint4*)(ob + 4096 + k * 256 + swz * 16) = *(uint4*)lu;
}

// ---------------------------------------------------------------------------
// k_assign_mma2: 3xFP16 mma.sync GEMM + argmax, A resident in smem.
// score = (2x | 1) . (e | -|e|^2)  -> accumulators are final scores.
// CTA = 64 pixels; A hi/lo for ALL 17 k-chunks converted ONCE into smem.
// Mainloop streams B only: 8 N-tile-pairs (256 codes) x 17 kc = 136 iters.
// 8 warps as 2M x 4N; warp tile 32 pixels x 64 codes; c[2][8][4] = 64 regs.
// ---------------------------------------------------------------------------
__global__ __launch_bounds__(256, 2) void k_assign_mma2(const float* __restrict__ x,
                                                        float* __restrict__ out_ids) {
    extern __shared__ __align__(16) unsigned char smdyn[];
    const uint32_t sbase = smem_u32(smdyn);
    const uint32_t APL = sbase + APL_OFF;
    const uint32_t BST = sbase + BST_OFF;
    const int tid = threadIdx.x;
    const int lane = tid & 31, wid = tid >> 5;
    const int wm0 = (wid >> 2) * 32;     // warp pixel base (2 groups of 32)
    const int ncol = wid & 3;
    const int wn0 = ncol * 64;           // warp code base within the 256-code stage
    const int mblk = blockIdx.x;

#define ISSUE_B2(stg, ntp_, kc_) do { \
        uint32_t db = BST + (stg) * 16384 + tid * 16; \
        const unsigned char* s0 = g_Bpl + ((size_t)(((ntp_) * 2 + 0) * NKC + (kc_)) << 13) + tid * 16; \
        const unsigned char* s1 = g_Bpl + ((size_t)(((ntp_) * 2 + 1) * NKC + (kc_)) << 13) + tid * 16; \
        CP16(db,          s0); \
        CP16(db + 4096,   s0 + 4096); \
        CP16(db + 8192,   s1); \
        CP16(db + 12288,  s1 + 4096); \
        CP_COMMIT(); \
    } while (0)

    ISSUE_B2(0, 0, 0);

    // ---- Phase 1: convert A once. thread -> (pixel p, q in 0..3 = (kc-pair half, oct)) ----
    {
        const int p = tid & 63;
        const int q = tid >> 6;
        const int m = mblk * 64 + p;
        const float* xs = x + (m >> 12) * (CC * HWS) + (m & 4095);
        for (int base = 0; base < NKC; base += 2) {
            const int kc = base + (q >> 1);
            const int oct = q & 1;
            if (kc < NKC) {
                uint32_t hu[4], lu[4];
#pragma unroll
                for (int kk = 0; kk < 8; kk += 2) {
                    const int ka = kc * 16 + oct * 8 + kk, kb = ka + 1;
                    float v0 = (ka < 256) ? 2.f * xs[(size_t)ka * HWS] : (ka == 256 ? 1.f : 0.f);
                    float v1 = (kb < 256) ? 2.f * xs[(size_t)kb * HWS] : (kb == 256 ? 1.f : 0.f);
                    __half h0 = __float2half_rn(v0), h1 = __float2half_rn(v1);
                    __half l0 = __float2half_rn(v0 - __half2float(h0));
                    __half l1 = __float2half_rn(v1 - __half2float(h1));
                    hu[kk >> 1] = (uint32_t)__half_as_ushort(h0) | ((uint32_t)__half_as_ushort(h1) << 16);
                    lu[kk >> 1] = (uint32_t)__half_as_ushort(l0) | ((uint32_t)__half_as_ushort(l1) << 16);
                }
                *(uint4*)(smdyn + APL_OFF + kc * 4096 + oct * 1024 + p * 16)        = *(uint4*)hu;
                *(uint4*)(smdyn + APL_OFF + kc * 4096 + 2048 + oct * 1024 + p * 16) = *(uint4*)lu;
            }
        }
    }

    float c[2][8][4];
#pragma unroll
    for (int a = 0; a < 2; a++)
#pragma unroll
        for (int b = 0; b < 8; b++)
#pragma unroll
            for (int r = 0; r < 4; r++) c[a][b][r] = 0.f;
    float bestS[4];
    int   bestI[4];
#pragma unroll
    for (int r = 0; r < 4; r++) { bestS[r] = -3.4e38f; bestI[r] = 0; }

    // ---- Phase 2: mainloop (B streaming only) ----
    const int g = lane >> 3;
    const int kk2 = ((g & 1) << 3) | (lane & 7);
    const int nbg = g >> 1;
    const int h = wn0 >> 7;          // which 8KB chunk within the stage
    const int ln0 = wn0 & 127;       // local code base within chunk

    for (int idx = 0; idx < NIT; idx++) {
        const int ntp = idx / NKC, kc = idx % NKC;
        __syncthreads();                       // retires idx-1 consumption (idx=0: publishes A)
        if (idx < NIT - 1) {
            const int i2 = idx + 1;
            ISSUE_B2(i2 & 1, i2 / NKC, i2 % NKC);
            CP_WAIT1();
        } else {
            CP_WAIT0();
        }
        __syncthreads();                       // B(idx) visible to all

        const uint32_t sB = BST + (idx & 1) * 16384 + h * 8192;

        // B fragments: [plane][unit-pair 4][4 regs]
        uint32_t bf[2][4][4];
#pragma unroll
        for (int pp = 0; pp < 2; pp++)
#pragma unroll
            for (int np = 0; np < 4; np++) {
                const int nblk = ((ln0 + np * 16) >> 3) + nbg;
                const uint32_t addr = sB + pp * 4096 + kk2 * 256 +
                    (((nblk & 8) | ((nblk ^ (kk2 & 7)) & 7)) << 4);
                LDSM_X4_T(bf[pp][np][0], bf[pp][np][1], bf[pp][np][2], bf[pp][np][3], addr);
            }
#pragma unroll
        for (int mt = 0; mt < 2; mt++) {
            const int mrow = wm0 + mt * 16 + (g & 1) * 8 + (lane & 7);
            uint32_t aH[4], aL[4];
            const uint32_t aaddr = APL + kc * 4096 + (g >> 1) * 1024 + mrow * 16;
            LDSM_X4(aH[0], aH[1], aH[2], aH[3], aaddr);
            LDSM_X4(aL[0], aL[1], aL[2], aL[3], aaddr + 2048);
#pragma unroll
            for (int np = 0; np < 4; np++) {
                MMA16816(c[mt][2*np],   aH[0],aH[1],aH[2],aH[3], bf[0][np][0], bf[0][np][1]);
                MMA16816(c[mt][2*np],   aH[0],aH[1],aH[2],aH[3], bf[1][np][0], bf[1][np][1]);
                MMA16816(c[mt][2*np],   aL[0],aL[1],aL[2],aL[3], bf[0][np][0], bf[0][np][1]);
                MMA16816(c[mt][2*np+1], aH[0],aH[1],aH[2],aH[3], bf[0][np][2], bf[0][np][3]);
                MMA16816(c[mt][2*np+1], aH[0],aH[1],aH[2],aH[3], bf[1][np][2], bf[1][np][3]);
                MMA16816(c[mt][2*np+1], aL[0],aL[1],aL[2],aL[3], bf[0][np][2], bf[0][np][3]);
            }
        }

        if (kc == NKC - 1) {
            // accumulators ARE the scores; running argmax (ascending n, strict >), reset
            const int nb0 = ntp * 256 + wn0 + (lane & 3) * 2;
#pragma unroll
            for (int mt = 0; mt < 2; mt++)
#pragma unroll
                for (int tn = 0; tn < 8; tn++) {
                    const int n = nb0 + tn * 8;
                    const float s0 = c[mt][tn][0];
                    const float s1 = c[mt][tn][1];
                    const float s2 = c[mt][tn][2];
                    const float s3 = c[mt][tn][3];
                    const int b0 = mt * 2, b1 = mt * 2 + 1;
                    if (s0 > bestS[b0]) { bestS[b0] = s0; bestI[b0] = n; }
                    if (s1 > bestS[b0]) { bestS[b0] = s1; bestI[b0] = n + 1; }
                    if (s2 > bestS[b1]) { bestS[b1] = s2; bestI[b1] = n; }
                    if (s3 > bestS[b1]) { bestS[b1] = s3; bestI[b1] = n + 1; }
                    c[mt][tn][0] = 0.f; c[mt][tn][1] = 0.f;
                    c[mt][tn][2] = 0.f; c[mt][tn][3] = 0.f;
                }
        }
    }

    __syncthreads();  // drained
    float* redS = (float*)(smdyn + RED_OFF);          // [4][64]
    int*   redI = (int*)(smdyn + RED_OFF + 1024);     // [4][64]

    // reduce across lane quads (lanes 4q..4q+3 share the same pixel rows)
    float rs[4]; int ri[4];
#pragma unroll
    for (int r = 0; r < 4; r++) {
        float s = bestS[r]; int i = bestI[r];
#pragma unroll
        for (int off = 1; off <= 2; off <<= 1) {
            float so = __shfl_xor_sync(0xffffffffu, s, off);
            int   io = __shfl_xor_sync(0xffffffffu, i, off);
            if (so > s || (so == s && io < i)) { s = so; i = io; }
        }
        rs[r] = s; ri[r] = i;
    }
    if ((lane & 3) == 0) {
#pragma unroll
        for (int r = 0; r < 4; r++) {
            const int rl = wm0 + (r >> 1) * 16 + (r & 1) * 8 + (lane >> 2);
            redS[ncol * 64 + rl] = rs[r];
            redI[ncol * 64 + rl] = ri[r];
        }
    }
    __syncthreads();
    if (ncol == 0 && (lane & 3) == 0) {
#pragma unroll
        for (int r = 0; r < 4; r++) {
            const int rl = wm0 + (r >> 1) * 16 + (r & 1) * 8 + (lane >> 2);
            float s = redS[rl]; int i = redI[rl];
#pragma unroll
            for (int cix = 1; cix < 4; cix++) {
                const float so = redS[cix * 64 + rl];
                const int   io = redI[cix * 64 + rl];
                if (so > s || (so == s && io < i)) { s = so; i = io; }
            }
            const int mm = mblk * 64 + rl;
            g_ids[mm] = i;
            const int sp = mm & 4095;
            out_ids[(mm & ~4095) | ((sp & 63) << 6) | (sp >> 6)] = (float)i;
        }
    }
}

// ---------------------------------------------------------------------------
// K2: quantized write + commit-loss SSE + segment sums (proven R1 code)
// ---------------------------------------------------------------------------
__global__ __launch_bounds__(256)
void k_quant(const float* __restrict__ x, const float* __restrict__ embed,
             float* __restrict__ out_q) {
    __shared__ float qs[32][257];
    __shared__ int   sid[32];
    __shared__ float red[8];

    const int t = threadIdx.x;
    const int lane = t & 31, warp = t >> 5;
    const int m0 = blockIdx.x * 32;
    const int b = m0 >> 12;
    const int s0 = m0 & 4095;

    if (t < 32) sid[t] = g_ids[m0 + t];
    __syncthreads();
#pragma unroll
    for (int r = 0; r < 4; r++) {
        const int pp = warp + r * 8;
        const float* row = embed + sid[pp] * CC;
#pragma unroll
        for (int jj = 0; jj < 8; jj++) qs[pp][lane + 32 * jj] = row[lane + 32 * jj];
    }
    __syncthreads();

    const float* xb = x + b * (CC * HWS) + s0;
    float* qb = out_q + b * (CC * HWS) + s0;
    const int myid = sid[lane];
    float lsum = 0.f;
#pragma unroll
    for (int ci = 0; ci < 32; ci++) {
        const int cc = warp + ci * 8;
        float xv = xb[cc * HWS + lane];
        float qv = qs[lane][cc];
        qb[cc * HWS + lane] = qv;
        float dd = xv - qv;
        lsum = fmaf(dd, dd, lsum);
        atomicAdd(&g_embed_sum[cc * DD + myid], xv);
    }
    if (warp == 0) atomicAdd(&g_counts[myid], 1.0f);

#pragma unroll
    for (int o = 16; o; o >>= 1) lsum += __shfl_xor_sync(0xffffffffu, lsum, o);
    if (lane == 0) red[warp] = lsum;
    __syncthreads();
    if (t == 0) {
        float s = 0.f;
#pragma unroll
        for (int i = 0; i < 8; i++) s += red[i];
        atomicAdd(&g_sse, s);
    }
}

__global__ void k_stats(const float* __restrict__ cs, float* __restrict__ out_ncs,
                        float* __restrict__ out_loss) {
    __shared__ float red[32];
    const int t = threadIdx.x;
    const int d0 = t, d1 = t + 1024;
    float n0 = MOM * cs[d0] + OMM * g_counts[d0];
    float n1 = MOM * cs[d1] + OMM * g_counts[d1];
    out_ncs[d0] = n0;
    out_ncs[d1] = n1;
    float s = n0 + n1;
#pragma unroll
    for (int o = 16; o; o >>= 1) s += __shfl_xor_sync(0xffffffffu, s, o);
    if ((t & 31) == 0) red[t >> 5] = s;
    __syncthreads();
    if (t < 32) {
        float v = red[t];
#pragma unroll
        for (int o = 16; o; o >>= 1) v += __shfl_xor_sync(0xffffffffu, v, o);
        if (t == 0) red[0] = v;
    }
    __syncthreads();
    const float n = red[0];
    const float scale = (n + (float)DD * EPSV) / n;
    g_inv_cs[d0] = scale / (n0 + EPSV);
    g_inv_cs[d1] = scale / (n1 + EPSV);
    if (t == 0) out_loss[0] = g_sse * (1.f / 16777216.f);
}

__global__ void k_embed_out(const float* __restrict__ embed_avg,
                            float* __restrict__ out_nea, float* __restrict__ out_ne) {
    const int idx = blockIdx.x * 256 + threadIdx.x;
    const int cc = idx >> 11, d = idx & 2047;
    float nea = MOM * embed_avg[idx] + OMM * g_embed_sum[idx];
    out_nea[idx] = nea;
    out_ne[d * CC + cc] = nea * g_inv_cs[d];
}

// ---------------------------------------------------------------------------
extern "C" void kernel_launch(void* const* d_in, const int* in_sizes, int n_in,
                              void* d_out, int out_size) {
    const float* x     = (const float*)d_in[0];
    const float* embed = (const float*)d_in[1];
    const float* cs    = (const float*)d_in[2];
    const float* ea    = (const float*)d_in[3];
    float* out = (float*)d_out;

    // Opt-in dynamic smem (idempotent; no static guards)
    cudaFuncSetAttribute(k_assign_mma2, cudaFuncAttributeMaxDynamicSharedMemorySize, SMEM_DYN);

    k_zero<<<(CC * DD + DD + 1 + 255) / 256, 256>>>();
    k_norm<<<DD / 8, 256>>>(embed);
    prep_B<<<16 * NKC, 256>>>(embed);
    k_assign_mma2<<<NPIX / 64, 256, SMEM_DYN>>>(x, out + OFF_IDS);
    k_quant<<<NPIX / 32, 256>>>(x, embed, out + OFF_Q);
    k_stats<<<1, 1024>>>(cs, out + OFF_NCS, out + OFF_LOSS);
    k_embed_out<<<(CC * DD) / 256, 256>>>(ea, out + OFF_NEA, out + OFF_NE);
}

// round 8
// speedup vs baseline: 2.8432x; 1.0347x over previous
#include <cuda_runtime.h>
#include <cuda_fp16.h>
#include <cstdint>

// Problem constants
#define BB 16
#define CC 256
#define HWS 4096
#define NPIX 65536
#define DD 2048
#define MOM 0.99f
#define OMM 0.01f
#define EPSV 1e-5f

// Output layout (float32, reference return order)
#define OFF_Q    0
#define OFF_LOSS 16777216
#define OFF_IDS  16777217
#define OFF_NE   16842753
#define OFF_NCS  17367041
#define OFF_NEA  17369089

#define NKC 16   // K chunks of 16 (K=256; norm handled in epilogue)
#define NTP 8    // N-tile pairs (2048 codes / 256)
#define NIT (NTP * NKC)  // 128 mainloop iterations
#define NSTG 3   // cp.async pipeline stages

// Dynamic smem layout for k_assign_mma3 (per CTA = 114688 B -> 2 CTAs/SM)
#define APL_OFF 0        // A planes: [kc 16][plane 2][oct 2][px 64] x 16B = 65536
#define BST_OFF 65536    // B stages: 3 x 16384 = 49152
#define SMEM_DYN 114688

// Scratch (small device globals only)
__device__ __align__(16) unsigned char g_Bpl[16u*NKC*8192u]; // [ntile][kchunk] 8KB fp16 hi/lo embed planes
__device__ float g_embed_norm[DD];
__device__ int   g_ids[NPIX];
__device__ float g_counts[DD];
__device__ float g_embed_sum[CC * DD];
__device__ float g_inv_cs[DD];
__device__ float g_sse;

// ---------------- PTX helpers (sm_80-baseline features only) ----------------
__device__ __forceinline__ uint32_t smem_u32(const void* p) {
    uint32_t a;
    asm("{ .reg .u64 t; cvta.to.shared.u64 t, %1; cvt.u32.u64 %0, t; }" : "=r"(a) : "l"(p));
    return a;
}
#define CP16(dst, src) asm volatile("cp.async.cg.shared.global [%0], [%1], 16;" :: "r"(dst), "l"(src))
#define CP_COMMIT() asm volatile("cp.async.commit_group;" ::: "memory")
#define CP_WAIT1()  asm volatile("cp.async.wait_group 1;" ::: "memory")
#define CP_WAIT0()  asm volatile("cp.async.wait_group 0;" ::: "memory")

#define LDSM_X4(r0,r1,r2,r3,addr) \
    asm volatile("ldmatrix.sync.aligned.m8n8.x4.shared.b16 {%0,%1,%2,%3}, [%4];" \
        : "=r"(r0),"=r"(r1),"=r"(r2),"=r"(r3) : "r"(addr))
#define LDSM_X4_T(r0,r1,r2,r3,addr) \
    asm volatile("ldmatrix.sync.aligned.m8n8.x4.trans.shared.b16 {%0,%1,%2,%3}, [%4];" \
        : "=r"(r0),"=r"(r1),"=r"(r2),"=r"(r3) : "r"(addr))

#define MMA16816(c, a0,a1,a2,a3, b0,b1) \
    asm volatile("mma.sync.aligned.m16n8k16.row.col.f32.f16.f16.f32 " \
        "{%0,%1,%2,%3}, {%4,%5,%6,%7}, {%8,%9}, {%0,%1,%2,%3};" \
        : "+f"((c)[0]),"+f"((c)[1]),"+f"((c)[2]),"+f"((c)[3]) \
        : "r"(a0),"r"(a1),"r"(a2),"r"(a3),"r"(b0),"r"(b1))

// ---------------------------------------------------------------------------
__global__ void k_zero() {
    int idx = blockIdx.x * 256 + threadIdx.x;
    if (idx < CC * DD)            g_embed_sum[idx] = 0.f;
    else if (idx < CC * DD + DD)  g_counts[idx - CC * DD] = 0.f;
    else if (idx == CC * DD + DD) g_sse = 0.f;
}

__global__ void k_norm(const float* __restrict__ embed) {
    int warp = threadIdx.x >> 5, lane = threadIdx.x & 31;
    int d = blockIdx.x * 8 + warp;
    const float* row = embed + d * CC;
    float s = 0.f;
#pragma unroll
    for (int j = 0; j < 8; j++) { float v = row[lane + 32 * j]; s = fmaf(v, v, s); }
#pragma unroll
    for (int o = 16; o; o >>= 1) s += __shfl_xor_sync(0xffffffffu, s, o);
    if (lane == 0) g_embed_norm[d] = s;
}

// ---------------------------------------------------------------------------
// prep_B: embed -> fp16 hi/lo planes.
// Chunk (nt, kc) = 8KB: [plane 2][k 16][swizzled 16B unit = 8 consecutive n]
// ---------------------------------------------------------------------------
__global__ __launch_bounds__(256) void prep_B(const float* __restrict__ embed) {
    const int nt = blockIdx.x / NKC, kc = blockIdx.x % NKC;
    const int t = threadIdx.x;
    const int k = t >> 4, nblk = t & 15;
    const int kglob = kc * 16 + k;
    const int n0 = nt * 128 + nblk * 8;
    uint32_t hu[4], lu[4];
#pragma unroll
    for (int nn = 0; nn < 8; nn += 2) {
        float v0 = embed[(n0 + nn) * CC + kglob];
        float v1 = embed[(n0 + nn + 1) * CC + kglob];
        __half h0 = __float2half_rn(v0), h1 = __float2half_rn(v1);
        __half l0 = __float2half_rn(v0 - __half2float(h0));
        __half l1 = __float2half_rn(v1 - __half2float(h1));
        hu[nn >> 1] = (uint32_t)__half_as_ushort(h0) | ((uint32_t)__half_as_ushort(h1) << 16);
        lu[nn >> 1] = (uint32_t)__half_as_ushort(l0) | ((uint32_t)__half_as_ushort(l1) << 16);
    }
    const int swz = (nblk & 8) | ((nblk ^ (k & 7)) & 7);
    unsigned char* ob = g_Bpl + ((size_t)(nt * NKC + kc) << 13);
    *(uint4*)(ob + k * 256 + swz * 16) = *(uint4*)hu;
    *(uint4*)(ob + 4096 + k * 256 + swz * 16) = *(uint4*)lu;
}

// ---------------------------------------------------------------------------
// k_assign_mma3: 3xFP16 mma.sync GEMM + argmax; A resident in smem;
// 3-stage cp.async B pipeline with ONE barrier per iteration.
// score = (2x).e - |e|^2 (norm subtracted in epilogue via __ldg, L1-hit).
// CTA = 64 pixels; 8 warps as 2M x 4N; warp tile 32px x 64 codes.
// ---------------------------------------------------------------------------
__global__ __launch_bounds__(256, 2) void k_assign_mma3(const float* __restrict__ x,
                                                        float* __restrict__ out_ids) {
    extern __shared__ __align__(16) unsigned char smdyn[];
    const uint32_t sbase = smem_u32(smdyn);
    const uint32_t APL = sbase + APL_OFF;
    const uint32_t BST = sbase + BST_OFF;
    const int tid = threadIdx.x;
    const int lane = tid & 31, wid = tid >> 5;
    const int wm0 = (wid >> 2) * 32;     // warp pixel base
    const int ncol = wid & 3;
    const int wn0 = ncol * 64;           // warp code base within the 256-code stage
    const int mblk = blockIdx.x;

#define ISSUE_B3(stg, idx2) do { \
        const int ntp_ = (idx2) / NKC, kc_ = (idx2) % NKC; \
        uint32_t db = BST + (stg) * 16384 + tid * 16; \
        const unsigned char* s0 = g_Bpl + ((size_t)((ntp_ * 2 + 0) * NKC + kc_) << 13) + tid * 16; \
        const unsigned char* s1 = g_Bpl + ((size_t)((ntp_ * 2 + 1) * NKC + kc_) << 13) + tid * 16; \
        CP16(db,          s0); \
        CP16(db + 4096,   s0 + 4096); \
        CP16(db + 8192,   s1); \
        CP16(db + 12288,  s1 + 4096); \
        CP_COMMIT(); \
    } while (0)

    ISSUE_B3(0, 0);
    ISSUE_B3(1, 1);

    // ---- Phase 1: convert A once (2x-scaled hi/lo fp16 planes) ----
    {
        const int p = tid & 63;
        const int q = tid >> 6;            // (kc-half, oct)
        const int m = mblk * 64 + p;
        const float* xs = x + (m >> 12) * (CC * HWS) + (m & 4095);
#pragma unroll
        for (int base = 0; base < NKC; base += 2) {
            const int kc = base + (q >> 1);
            const int oct = q & 1;
            uint32_t hu[4], lu[4];
#pragma unroll
            for (int kk = 0; kk < 8; kk += 2) {
                const int ka = kc * 16 + oct * 8 + kk;
                float v0 = 2.f * xs[(size_t)ka * HWS];
                float v1 = 2.f * xs[(size_t)(ka + 1) * HWS];
                __half h0 = __float2half_rn(v0), h1 = __float2half_rn(v1);
                __half l0 = __float2half_rn(v0 - __half2float(h0));
                __half l1 = __float2half_rn(v1 - __half2float(h1));
                hu[kk >> 1] = (uint32_t)__half_as_ushort(h0) | ((uint32_t)__half_as_ushort(h1) << 16);
                lu[kk >> 1] = (uint32_t)__half_as_ushort(l0) | ((uint32_t)__half_as_ushort(l1) << 16);
            }
            *(uint4*)(smdyn + APL_OFF + kc * 4096 + oct * 1024 + p * 16)        = *(uint4*)hu;
            *(uint4*)(smdyn + APL_OFF + kc * 4096 + 2048 + oct * 1024 + p * 16) = *(uint4*)lu;
        }
    }

    float c[2][8][4];
#pragma unroll
    for (int a = 0; a < 2; a++)
#pragma unroll
        for (int b = 0; b < 8; b++)
#pragma unroll
            for (int r = 0; r < 4; r++) c[a][b][r] = 0.f;
    float bestS[4];
    int   bestI[4];
#pragma unroll
    for (int r = 0; r < 4; r++) { bestS[r] = -3.4e38f; bestI[r] = 0; }

    // ---- Phase 2: mainloop, ONE barrier per iteration ----
    const int g = lane >> 3;
    const int kk2 = ((g & 1) << 3) | (lane & 7);
    const int nbg = g >> 1;
    const int h = wn0 >> 7;          // which 8KB chunk within the stage
    const int ln0 = wn0 & 127;       // local code base within chunk

    int stg = 0;
    for (int idx = 0; idx < NIT; idx++) {
        const int ntp = idx / NKC, kc = idx % NKC;
        if (idx + 1 < NIT) CP_WAIT1(); else CP_WAIT0();   // stage(idx) landed (own groups)
        __syncthreads();                                   // visible to all; all done with idx-1
        if (idx + 2 < NIT) ISSUE_B3((stg + 2) % NSTG, idx + 2);  // slot freed at idx-1

        const uint32_t sB = BST + stg * 16384 + h * 8192;

        // B fragments: [plane][unit-pair 4][4 regs]
        uint32_t bf[2][4][4];
#pragma unroll
        for (int pp = 0; pp < 2; pp++)
#pragma unroll
            for (int np = 0; np < 4; np++) {
                const int nblk = ((ln0 + np * 16) >> 3) + nbg;
                const uint32_t addr = sB + pp * 4096 + kk2 * 256 +
                    (((nblk & 8) | ((nblk ^ (kk2 & 7)) & 7)) << 4);
                LDSM_X4_T(bf[pp][np][0], bf[pp][np][1], bf[pp][np][2], bf[pp][np][3], addr);
            }
#pragma unroll
        for (int mt = 0; mt < 2; mt++) {
            const int mrow = wm0 + mt * 16 + (g & 1) * 8 + (lane & 7);
            uint32_t aH[4], aL[4];
            const uint32_t aaddr = APL + kc * 4096 + (g >> 1) * 1024 + mrow * 16;
            LDSM_X4(aH[0], aH[1], aH[2], aH[3], aaddr);
            LDSM_X4(aL[0], aL[1], aL[2], aL[3], aaddr + 2048);
#pragma unroll
            for (int np = 0; np < 4; np++) {
                MMA16816(c[mt][2*np],   aH[0],aH[1],aH[2],aH[3], bf[0][np][0], bf[0][np][1]);
                MMA16816(c[mt][2*np],   aH[0],aH[1],aH[2],aH[3], bf[1][np][0], bf[1][np][1]);
                MMA16816(c[mt][2*np],   aL[0],aL[1],aL[2],aL[3], bf[0][np][0], bf[0][np][1]);
                MMA16816(c[mt][2*np+1], aH[0],aH[1],aH[2],aH[3], bf[0][np][2], bf[0][np][3]);
                MMA16816(c[mt][2*np+1], aH[0],aH[1],aH[2],aH[3], bf[1][np][2], bf[1][np][3]);
                MMA16816(c[mt][2*np+1], aL[0],aL[1],aL[2],aL[3], bf[0][np][2], bf[0][np][3]);
            }
        }

        if (kc == NKC - 1) {
            // scores = c - |e|^2; running argmax (ascending n, strict >), reset
            const int nb0 = ntp * 256 + wn0 + (lane & 3) * 2;
#pragma unroll
            for (int tn = 0; tn < 8; tn++) {
                const int n = nb0 + tn * 8;
                const float nr0 = __ldg(&g_embed_norm[n]);
                const float nr1 = __ldg(&g_embed_norm[n + 1]);
#pragma unroll
                for (int mt = 0; mt < 2; mt++) {
                    const float s0 = c[mt][tn][0] - nr0;
                    const float s1 = c[mt][tn][1] - nr1;
                    const float s2 = c[mt][tn][2] - nr0;
                    const float s3 = c[mt][tn][3] - nr1;
                    const int b0 = mt * 2, b1 = mt * 2 + 1;
                    if (s0 > bestS[b0]) { bestS[b0] = s0; bestI[b0] = n; }
                    if (s1 > bestS[b0]) { bestS[b0] = s1; bestI[b0] = n + 1; }
                    if (s2 > bestS[b1]) { bestS[b1] = s2; bestI[b1] = n; }
                    if (s3 > bestS[b1]) { bestS[b1] = s3; bestI[b1] = n + 1; }
                    c[mt][tn][0] = 0.f; c[mt][tn][1] = 0.f;
                    c[mt][tn][2] = 0.f; c[mt][tn][3] = 0.f;
                }
            }
        }
        stg = (stg + 1) % NSTG;
    }

    __syncthreads();  // drained; reuse A-plane smem for cross-warp reduce
    float* redS = (float*)smdyn;             // [4][64]
    int*   redI = (int*)(smdyn + 1024);      // [4][64]

    // reduce across lane quads (lanes 4q..4q+3 share the same pixel rows)
    float rs[4]; int ri[4];
#pragma unroll
    for (int r = 0; r < 4; r++) {
        float s = bestS[r]; int i = bestI[r];
#pragma unroll
        for (int off = 1; off <= 2; off <<= 1) {
            float so = __shfl_xor_sync(0xffffffffu, s, off);
            int   io = __shfl_xor_sync(0xffffffffu, i, off);
            if (so > s || (so == s && io < i)) { s = so; i = io; }
        }
        rs[r] = s; ri[r] = i;
    }
    if ((lane & 3) == 0) {
#pragma unroll
        for (int r = 0; r < 4; r++) {
            const int rl = wm0 + (r >> 1) * 16 + (r & 1) * 8 + (lane >> 2);
            redS[ncol * 64 + rl] = rs[r];
            redI[ncol * 64 + rl] = ri[r];
        }
    }
    __syncthreads();
    if (ncol == 0 && (lane & 3) == 0) {
#pragma unroll
        for (int r = 0; r < 4; r++) {
            const int rl = wm0 + (r >> 1) * 16 + (r & 1) * 8 + (lane >> 2);
            float s = redS[rl]; int i = redI[rl];
#pragma unroll
            for (int cix = 1; cix < 4; cix++) {
                const float so = redS[cix * 64 + rl];
                const int   io = redI[cix * 64 + rl];
                if (so > s || (so == s && io < i)) { s = so; i = io; }
            }
            const int mm = mblk * 64 + rl;
            g_ids[mm] = i;
            const int sp = mm & 4095;
            out_ids[(mm & ~4095) | ((sp & 63) << 6) | (sp >> 6)] = (float)i;
        }
    }
}

// ---------------------------------------------------------------------------
// K2: quantized write + commit-loss SSE + segment sums (proven R1 code)
// ---------------------------------------------------------------------------
__global__ __launch_bounds__(256)
void k_quant(const float* __restrict__ x, const float* __restrict__ embed,
             float* __restrict__ out_q) {
    __shared__ float qs[32][257];
    __shared__ int   sid[32];
    __shared__ float red[8];

    const int t = threadIdx.x;
    const int lane = t & 31, warp = t >> 5;
    const int m0 = blockIdx.x * 32;
    const int b = m0 >> 12;
    const int s0 = m0 & 4095;

    if (t < 32) sid[t] = g_ids[m0 + t];
    __syncthreads();
#pragma unroll
    for (int r = 0; r < 4; r++) {
        const int pp = warp + r * 8;
        const float* row = embed + sid[pp] * CC;
#pragma unroll
        for (int jj = 0; jj < 8; jj++) qs[pp][lane + 32 * jj] = row[lane + 32 * jj];
    }
    __syncthreads();

    const float* xb = x + b * (CC * HWS) + s0;
    float* qb = out_q + b * (CC * HWS) + s0;
    const int myid = sid[lane];
    float lsum = 0.f;
#pragma unroll
    for (int ci = 0; ci < 32; ci++) {
        const int cc = warp + ci * 8;
        float xv = xb[cc * HWS + lane];
        float qv = qs[lane][cc];
        qb[cc * HWS + lane] = qv;
        float dd = xv - qv;
        lsum = fmaf(dd, dd, lsum);
        atomicAdd(&g_embed_sum[cc * DD + myid], xv);
    }
    if (warp == 0) atomicAdd(&g_counts[myid], 1.0f);

#pragma unroll
    for (int o = 16; o; o >>= 1) lsum += __shfl_xor_sync(0xffffffffu, lsum, o);
    if (lane == 0) red[warp] = lsum;
    __syncthreads();
    if (t == 0) {
        float s = 0.f;
#pragma unroll
        for (int i = 0; i < 8; i++) s += red[i];
        atomicAdd(&g_sse, s);
    }
}

__global__ void k_stats(const float* __restrict__ cs, float* __restrict__ out_ncs,
                        float* __restrict__ out_loss) {
    __shared__ float red[32];
    const int t = threadIdx.x;
    const int d0 = t, d1 = t + 1024;
    float n0 = MOM * cs[d0] + OMM * g_counts[d0];
    float n1 = MOM * cs[d1] + OMM * g_counts[d1];
    out_ncs[d0] = n0;
    out_ncs[d1] = n1;
    float s = n0 + n1;
#pragma unroll
    for (int o = 16; o; o >>= 1) s += __shfl_xor_sync(0xffffffffu, s, o);
    if ((t & 31) == 0) red[t >> 5] = s;
    __syncthreads();
    if (t < 32) {
        float v = red[t];
#pragma unroll
        for (int o = 16; o; o >>= 1) v += __shfl_xor_sync(0xffffffffu, v, o);
        if (t == 0) red[0] = v;
    }
    __syncthreads();
    const float n = red[0];
    const float scale = (n + (float)DD * EPSV) / n;
    g_inv_cs[d0] = scale / (n0 + EPSV);
    g_inv_cs[d1] = scale / (n1 + EPSV);
    if (t == 0) out_loss[0] = g_sse * (1.f / 16777216.f);
}

__global__ void k_embed_out(const float* __restrict__ embed_avg,
                            float* __restrict__ out_nea, float* __restrict__ out_ne) {
    const int idx = blockIdx.x * 256 + threadIdx.x;
    const int cc = idx >> 11, d = idx & 2047;
    float nea = MOM * embed_avg[idx] + OMM * g_embed_sum[idx];
    out_nea[idx] = nea;
    out_ne[d * CC + cc] = nea * g_inv_cs[d];
}

// ---------------------------------------------------------------------------
extern "C" void kernel_launch(void* const* d_in, const int* in_sizes, int n_in,
                              void* d_out, int out_size) {
    const float* x     = (const float*)d_in[0];
    const float* embed = (const float*)d_in[1];
    const float* cs    = (const float*)d_in[2];
    const float* ea    = (const float*)d_in[3];
    float* out = (float*)d_out;

    cudaFuncSetAttribute(k_assign_mma3, cudaFuncAttributeMaxDynamicSharedMemorySize, SMEM_DYN);

    k_zero<<<(CC * DD + DD + 1 + 255) / 256, 256>>>();
    k_norm<<<DD / 8, 256>>>(embed);
    prep_B<<<16 * NKC, 256>>>(embed);
    k_assign_mma3<<<NPIX / 64, 256, SMEM_DYN>>>(x, out + OFF_IDS);
    k_quant<<<NPIX / 32, 256>>>(x, embed, out + OFF_Q);
    k_stats<<<1, 1024>>>(cs, out + OFF_NCS, out + OFF_LOSS);
    k_embed_out<<<(CC * DD) / 256, 256>>>(ea, out + OFF_NEA, out + OFF_NE);
}